// round 14
// baseline (speedup 1.0000x reference)
#include <cuda_runtime.h>
#include <cstdint>
#include <math.h>

#define BB 8
#define CC 4
#define HH 96
#define WW 96
#define HW_ (HH*WW)
#define NC 3                    // classes 1..3 (class 0 ignored)
#define CAP 1024                // hist bins: squared dist < 1024 (dist<=31), astronomically safe
#define NPAIR (BB*NC)           // 24 (img, class) units == clusters
#define NBLK 144                // 24 clusters x 6 CTAs (dir x slice)
#define CLS 6
#define NT 1024
#define SENT 30000              // sentinel: empty row (> 95^2)
#define NWORDS (HW_/32)         // 288 mask words per (m,b,c)
#define AM_PX 512               // argmax pixels per block (one latency round)

// dynamic smem: hist[CAP] (dir0), hist2[CAP] (dir1, rank0 only), rowd[HH][WW] u16
#define HIST2_OFF (CAP*4)
#define ROWD_OFF  (2*CAP*4)
#define SMEM_BYTES (ROWD_OFF + HW_*2)     // 26,624 B

__device__ unsigned int g_bits[2][BB][NC][NWORDS];  // [0]=pred mask A, [1]=label mask B
__device__ float        g_acc[3][NC];               // sums over b: [0]=F,[1]=R,[2]=M (reset at end)
__device__ unsigned int g_img[BB];                  // per-image producer counters (reset at end)
__device__ unsigned int g_ticket = 0;               // finalize election (wraps at NPAIR)

#define CLUSTER_SYNC() do { \
    asm volatile("barrier.cluster.arrive.aligned;" ::: "memory"); \
    asm volatile("barrier.cluster.wait.aligned;"   ::: "memory"); \
} while (0)

__device__ __forceinline__ unsigned int smem_u32(const void* p) {
    unsigned int a;
    asm("{ .reg .u64 t; cvta.to.shared.u64 t, %1; cvt.u32.u64 %0, t; }" : "=r"(a) : "l"(p));
    return a;
}
// atomic add into the SAME smem offset of cluster rank 0
__device__ __forceinline__ void red_rank0_add(unsigned int local_addr, unsigned int val) {
    asm volatile("{ .reg .b32 r; mapa.shared::cluster.u32 r, %0, %1; red.shared::cluster.add.u32 [r], %2; }"
                 :: "r"(local_addr), "r"(0u), "r"(val) : "memory");
}

// EDT query: min over rows y' of (y-y')^2 + rowdist2[y'][x]; early exit when rr^2 >= best.
__device__ __forceinline__ int edt2q(const unsigned short* __restrict__ col, int y) {
    int e = col[y * WW];
#pragma unroll 4
    for (int rr = 1; rr < HH; rr++) {
        int r2 = rr * rr;
        if (r2 >= e) break;
        int up = y - rr, dn = y + rr;
        if (up >= 0) e = min(e, r2 + (int)col[up * WW]);
        if (dn < HH) e = min(e, r2 + (int)col[dn * WW]);
    }
    return e;
}

// nearest set bit <= x in 96-bit mask; very-negative if none
__device__ __forceinline__ int nearest_left(unsigned b0, unsigned b1, unsigned b2, int x) {
    int j = x >> 5, o = x & 31;
    unsigned w[3] = { b0, b1, b2 };
    unsigned m = w[j] & (0xFFFFFFFFu >> (31 - o));
    if (m) return (j << 5) + 31 - __clz(m);
#pragma unroll
    for (int k = 1; k >= 0; k--)
        if (k < j && w[k]) return (k << 5) + 31 - __clz(w[k]);
    return -1000;
}
// nearest set bit >= x; very-positive if none
__device__ __forceinline__ int nearest_right(unsigned b0, unsigned b1, unsigned b2, int x) {
    int j = x >> 5, o = x & 31;
    unsigned w[3] = { b0, b1, b2 };
    unsigned m = w[j] & (0xFFFFFFFFu << o);
    if (m) return (j << 5) + __ffs(m) - 1;
#pragma unroll
    for (int k = 1; k < 3; k++)
        if (k > j && w[k]) return (k << 5) + __ffs(w[k]) - 1;
    return 1000;
}

__global__ void __launch_bounds__(NT, 1) __cluster_dims__(CLS, 1, 1)
k_all(const float* __restrict__ pred, const int* __restrict__ labels,
      float* __restrict__ out)
{
    extern __shared__ unsigned char smem[];
    unsigned int*   hist  = (unsigned int*)smem;                  // [CAP] own EDT hist / rank0 dir0
    unsigned int*   hist2 = (unsigned int*)(smem + HIST2_OFF);    // [CAP] rank0 dir1 merge target
    unsigned short* rowd  = (unsigned short*)(smem + ROWD_OFF);   // [HH][WW]

    __shared__ unsigned int bits[2][HH][3];
    __shared__ unsigned int warp_scan[32];
    __shared__ unsigned int s_total;
    __shared__ int s_bin[2];

    int t = threadIdx.x;
    int lane = t & 31, wid = t >> 5;
    int bx = blockIdx.x;
    int img = bx / 18, sub = bx - img * 18;
    int pl = sub / 6;                 // class index 0..2
    int rank = sub % 6;               // cluster rank
    int dir = rank / 3;               // 0: fwd (A->B), 1: rev (B->A)
    int slice = rank % 3;
    int c = pl + 1, b = img;
    int qm = dir;                     // query mask: fwd->A(0), rev->B(1)
    int tm = dir ^ 1;                 // target (EDT of): fwd->B(1), rev->A(0)

    // ================= PHASE A: argmax slice (512 px, one round) =================
    {
        const float* pb = pred + (size_t)img * CC * HW_;
        const int*   lb = labels + (size_t)img * HW_;
        if (t < AM_PX) {
            int pix = sub * AM_PX + t;
            float v0 = pb[pix];
            float v1 = pb[HW_ + pix];
            float v2 = pb[2 * HW_ + pix];
            float v3 = pb[3 * HW_ + pix];
            int li = lb[pix];
            float best = v0; int bi = 0;
            if (v1 > best) { best = v1; bi = 1; }      // strict > : first-occurrence argmax
            if (v2 > best) { best = v2; bi = 2; }
            if (v3 > best) { best = v3; bi = 3; }
            int w = pix >> 5;
#pragma unroll
            for (int cc = 1; cc <= NC; cc++) {
                unsigned wa = __ballot_sync(0xffffffffu, bi == cc);
                unsigned wb = __ballot_sync(0xffffffffu, li == cc);
                if (lane == 0) {
                    g_bits[0][img][cc - 1][w] = wa;
                    g_bits[1][img][cc - 1][w] = wb;
                }
            }
        }
        // clear both smem hists (2048 words = 512 uint4)
        if (t < 512) ((uint4*)hist)[t] = make_uint4(0u, 0u, 0u, 0u);
    }
    __syncthreads();
    if (t == 0) {
        __threadfence();
        atomicAdd(&g_img[img], 1u);
        while (atomicAdd(&g_img[img], 0u) < 18u) __nanosleep(32);   // reset each replay
        __threadfence();
    }
    __syncthreads();

    // ================= PHASE B: bits -> rowdist -> EDT slice =================
    {
        unsigned int* bl = &bits[0][0][0];             // [2][HH][3] linear
        if (t < 2 * NWORDS) {
            int m = t / NWORDS, w = t - m * NWORDS;
            bl[t] = g_bits[m][b][c - 1][w];
        }
    }
    __syncthreads();

    // 1D row distance of TARGET mask, 8 px/thread with propagation
    for (int idx = t; idx < HW_ / 8; idx += NT) {      // 1152 groups
        int y = idx / 12, g = idx - y * 12;
        int x0 = g << 3;
        unsigned b0 = bits[tm][y][0], b1 = bits[tm][y][1], b2 = bits[tm][y][2];
        unsigned w3[3] = { b0, b1, b2 };
        unsigned nib = (w3[x0 >> 5] >> (x0 & 31)) & 0xFFu;

        int dl = x0 - nearest_left(b0, b1, b2, x0);
        int dr = nearest_right(b0, b1, b2, x0 + 7) - (x0 + 7);

        int dlv[8], drv[8];
        dlv[0] = dl;
#pragma unroll
        for (int i = 1; i < 8; i++) dlv[i] = ((nib >> i) & 1u) ? 0 : dlv[i - 1] + 1;
        drv[7] = dr;
#pragma unroll
        for (int i = 6; i >= 0; i--) drv[i] = ((nib >> i) & 1u) ? 0 : drv[i + 1] + 1;

        unsigned v[8];
#pragma unroll
        for (int i = 0; i < 8; i++) {
            int d = min(dlv[i], drv[i]);
            v[i] = (d > 95) ? (unsigned)SENT : (unsigned)(d * d);
        }
        uint4 pk;
        pk.x = v[0] | (v[1] << 16);
        pk.y = v[2] | (v[3] << 16);
        pk.z = v[4] | (v[5] << 16);
        pk.w = v[6] | (v[7] << 16);
        ((uint4*)rowd)[idx] = pk;
    }
    __syncthreads();

    // EDT queries for this slice's 3072 px (3 uniform iters) -> own smem hist
    {
        int base = slice * (HW_ / 3), end = base + HW_ / 3;
        for (int pix = base + t; pix < end; pix += NT) {
            int y = pix / WW, x = pix - y * WW;
            if ((bits[qm][y][x >> 5] >> (x & 31)) & 1u) {
                int e = edt2q(rowd + x, y);
                atomicAdd(&hist[min(e, CAP - 1)], 1u);
            }
        }
    }
    __syncthreads();

    // ================= DSMEM merge into rank 0 =================
    CLUSTER_SYNC();                                    // all 6 EDT hists complete
    if (rank != 0) {
        unsigned int v = hist[t];                      // 1 bin / thread, sparse
        if (v) {
            unsigned int addr = smem_u32(smem) + (dir ? HIST2_OFF : 0) + t * 4;
            red_rank0_add(addr, v);
        }
    }
    CLUSTER_SYNC();                                    // merges visible to rank 0
    if (rank != 0) return;

    // ================= PHASE C (rank 0): two percentiles + accumulate =================
    float vals[2];
#pragma unroll
    for (int d = 0; d < 2; d++) {
        const unsigned int* h = d ? hist2 : hist;
        unsigned int own = h[t];                       // 1 bin / thread

        unsigned int inc = own;
#pragma unroll
        for (int o = 1; o < 32; o <<= 1) {
            unsigned int v = __shfl_up_sync(0xffffffffu, inc, o);
            if (lane >= o) inc += v;
        }
        if (lane == 31) warp_scan[wid] = inc;
        __syncthreads();
        if (wid == 0) {
            unsigned int wv = warp_scan[lane];
            unsigned int wi = wv;
#pragma unroll
            for (int o = 1; o < 32; o <<= 1) {
                unsigned int v = __shfl_up_sync(0xffffffffu, wi, o);
                if (lane >= o) wi += v;
            }
            warp_scan[lane] = wi - wv;
            if (lane == 31) s_total = wi;
        }
        __syncthreads();
        unsigned int base = warp_scan[wid] + (inc - own);
        unsigned int mend = base + own;
        unsigned int n = s_total;

        int nm1 = (int)n - 1; if (nm1 < 0) nm1 = 0;
        float pos = 0.95f * (float)nm1;                // fp32, matches jnp
        int lo = (int)floorf(pos), hi = (int)ceilf(pos);
        float frac = pos - (float)lo;

        if (n > 0) {
            if ((unsigned int)lo >= base && (unsigned int)lo < mend) s_bin[0] = t;
            if ((unsigned int)hi >= base && (unsigned int)hi < mend) s_bin[1] = t;
        }
        __syncthreads();

        vals[d] = (n == 0) ? __int_as_float(0x7f800000)
                : sqrtf((float)s_bin[0]) * (1.0f - frac) + sqrtf((float)s_bin[1]) * frac;
        __syncthreads();                               // protect s_bin before pass 2
    }

    if (t == 0) {
        float f = vals[0], r = vals[1];
        atomicAdd(&g_acc[0][pl], f);
        atomicAdd(&g_acc[1][pl], r);
        atomicAdd(&g_acc[2][pl], fmaxf(f, r));
        __threadfence();
        unsigned int old = atomicInc(&g_ticket, NPAIR - 1);   // wraps -> replay-safe
        if (old == NPAIR - 1) {
            __threadfence();
            volatile float* ga = (volatile float*)&g_acc[0][0];
            float F[CC], R[CC], M[CC];
            F[0] = R[0] = M[0] = 0.0f;                        // ignored class
            for (int cc = 1; cc < CC; cc++) {
                F[cc] = ga[0 * NC + (cc - 1)] / (float)BB;
                R[cc] = ga[1 * NC + (cc - 1)] / (float)BB;
                M[cc] = ga[2 * NC + (cc - 1)] / (float)BB;
            }
            const float* vs[3] = { M, F, R };                 // MHD, FHD, RHD
            for (int k = 0; k < 3; k++) {
                const float* v = vs[k];
                float s = 0.f, s1v = 0.f;
                for (int cc = 0; cc < CC; cc++) {
                    out[k * 6 + cc] = v[cc];
                    s += v[cc];
                    if (cc >= 1) s1v += v[cc];
                }
                out[k * 6 + 4] = s / (float)CC;
                out[k * 6 + 5] = s1v / (float)(CC - 1);
            }
            // reset accumulators + producer counters for the next graph replay
            for (int i = 0; i < 3 * NC; i++) ((volatile float*)&g_acc[0][0])[i] = 0.0f;
            for (int i = 0; i < BB; i++) g_img[i] = 0u;
            __threadfence();
        }
    }
}

extern "C" void kernel_launch(void* const* d_in, const int* in_sizes, int n_in,
                              void* d_out, int out_size) {
    const float* pred   = (const float*)d_in[0];
    const int*   labels = (const int*)d_in[1];
    float*       out    = (float*)d_out;

    (void)cudaFuncSetAttribute(k_all, cudaFuncAttributeMaxDynamicSharedMemorySize, SMEM_BYTES);
    k_all<<<NBLK, NT, SMEM_BYTES>>>(pred, labels, out);
}

// round 15
// speedup vs baseline: 1.1425x; 1.1425x over previous
#include <cuda_runtime.h>
#include <cstdint>
#include <math.h>

#define BB 8
#define CC 4
#define HH 96
#define WW 96
#define HW_ (HH*WW)
#define NC 3                    // classes 1..3 (class 0 ignored)
#define CAP 1024                // hist bins: squared dist < 1024 (dist<=31), astronomically safe
#define NPAIR (BB*NC)           // 24
#define NBLK 144                // 8 images x 18 argmax slices == 24 pairs x 2 dirs x 3 slices
#define NBLK2 (NPAIR*2)         // 48 (pair,dir) units
#define NT 1024
#define SENT 30000              // sentinel: empty row (> 95^2)
#define NWORDS (HW_/32)         // 288 mask words per (m,b,c)
#define AM_PX 512               // argmax pixels per block (one latency round)
#define AM_PER_IMG 18

// dynamic smem: [CAP] uint32 histogram, then [HH][WW] uint16 row dists
#define ROWD_OFF (CAP*4)
#define SMEM_BYTES (ROWD_OFF + HW_*2)     // 22,528 B

__device__ unsigned int g_bits[2][BB][NC][NWORDS];  // [0]=pred mask A, [1]=label mask B
__device__ unsigned int g_hist[NBLK2][CAP];         // cleared in phase A each replay
__device__ float        g_fr[BB][NC][2];
__device__ unsigned int g_ticket = 0;               // finalize election (wraps at NBLK2)
__device__ unsigned int g_arrive = 0;               // grid barrier (monotonic -> replay-safe)

__device__ __forceinline__ void grid_barrier(int t) {
    __syncthreads();
    if (t == 0) {
        __threadfence();
        unsigned int v = atomicAdd(&g_arrive, 1u);
        unsigned int target = (v / NBLK + 1u) * NBLK;   // next multiple of NBLK
        while (atomicAdd(&g_arrive, 0u) < target) __nanosleep(64);
        __threadfence();
    }
    __syncthreads();
}

// EDT query: min over rows y' of (y-y')^2 + rowdist2[y'][x]; early exit when rr^2 >= best.
__device__ __forceinline__ int edt2q(const unsigned short* __restrict__ col, int y) {
    int e = col[y * WW];
#pragma unroll 4
    for (int rr = 1; rr < HH; rr++) {
        int r2 = rr * rr;
        if (r2 >= e) break;
        int up = y - rr, dn = y + rr;
        if (up >= 0) e = min(e, r2 + (int)col[up * WW]);
        if (dn < HH) e = min(e, r2 + (int)col[dn * WW]);
    }
    return e;
}

// nearest set bit <= x in 96-bit mask; very-negative if none
__device__ __forceinline__ int nearest_left(unsigned b0, unsigned b1, unsigned b2, int x) {
    int j = x >> 5, o = x & 31;
    unsigned w[3] = { b0, b1, b2 };
    unsigned m = w[j] & (0xFFFFFFFFu >> (31 - o));
    if (m) return (j << 5) + 31 - __clz(m);
#pragma unroll
    for (int k = 1; k >= 0; k--)
        if (k < j && w[k]) return (k << 5) + 31 - __clz(w[k]);
    return -1000;
}
// nearest set bit >= x; very-positive if none
__device__ __forceinline__ int nearest_right(unsigned b0, unsigned b1, unsigned b2, int x) {
    int j = x >> 5, o = x & 31;
    unsigned w[3] = { b0, b1, b2 };
    unsigned m = w[j] & (0xFFFFFFFFu << o);
    if (m) return (j << 5) + __ffs(m) - 1;
#pragma unroll
    for (int k = 1; k < 3; k++)
        if (k > j && w[k]) return (k << 5) + __ffs(w[k]) - 1;
    return 1000;
}

__global__ void __launch_bounds__(NT, 1)
k_all(const float* __restrict__ pred, const int* __restrict__ labels,
      float* __restrict__ out)
{
    extern __shared__ unsigned char smem[];
    unsigned int*   hist = (unsigned int*)smem;                  // [CAP]
    unsigned short* rowd = (unsigned short*)(smem + ROWD_OFF);   // [HH][WW] (target mask)

    __shared__ unsigned int bits[2][HH][3];
    __shared__ unsigned int warp_scan[32];
    __shared__ unsigned int s_total;
    __shared__ int s_bin[2];

    int t = threadIdx.x;
    int lane = t & 31, wid = t >> 5;
    int bx = blockIdx.x;

    // ================= PHASE A: argmax slice + clears =================
    {
        int img = bx / AM_PER_IMG, amslice = bx - img * AM_PER_IMG;
        const float* pb = pred + (size_t)img * CC * HW_;
        const int*   lb = labels + (size_t)img * HW_;
        if (t < AM_PX) {
            int pix = amslice * AM_PX + t;                // one latency round
            float v0 = pb[pix];
            float v1 = pb[HW_ + pix];
            float v2 = pb[2 * HW_ + pix];
            float v3 = pb[3 * HW_ + pix];
            int li = lb[pix];
            float best = v0; int bi = 0;
            if (v1 > best) { best = v1; bi = 1; }         // strict > : first-occurrence argmax
            if (v2 > best) { best = v2; bi = 2; }
            if (v3 > best) { best = v3; bi = 3; }
            int w = pix >> 5;
#pragma unroll
            for (int cc = 1; cc <= NC; cc++) {
                unsigned wa = __ballot_sync(0xffffffffu, bi == cc);
                unsigned wb = __ballot_sync(0xffffffffu, li == cc);
                if (lane == 0) {
                    g_bits[0][img][cc - 1][w] = wa;
                    g_bits[1][img][cc - 1][w] = wb;
                }
            }
        }
        // clear global hist (48*1024 words = 12288 uint4; one store for blocks 0-11)
        {
            int gi = bx * NT + t;
            if (gi < (NBLK2 * CAP) / 4)
                ((uint4*)&g_hist[0][0])[gi] = make_uint4(0u, 0u, 0u, 0u);
        }
        // clear smem hist (256 uint4)
        if (t < CAP / 4) ((uint4*)hist)[t] = make_uint4(0u, 0u, 0u, 0u);
    }

    grid_barrier(t);

    // ================= PHASE B: (pair,dir,slice) EDT -> smem hist -> global =================
    int pair = bx / 6, dir = (bx / 3) & 1, slice = bx % 3;
    int c = pair % NC + 1, b = pair / NC;
    int qm = dir;                                      // query mask: fwd->A(0), rev->B(1)
    int tm = dir ^ 1;                                  // target (EDT of): fwd->B(1), rev->A(0)
    int hid = pair * 2 + dir;

    {
        unsigned int* bl = &bits[0][0][0];             // [2][HH][3] linear
        if (t < 2 * NWORDS) {
            int m = t / NWORDS, w = t - m * NWORDS;
            bl[t] = g_bits[m][b][c - 1][w];
        }
    }
    __syncthreads();

    // 1D row distance of TARGET mask, 8 px/thread with propagation (1.125 iters)
    for (int idx = t; idx < HW_ / 8; idx += NT) {      // 1152 groups of 8 aligned px
        int y = idx / 12, g = idx - y * 12;
        int x0 = g << 3;
        unsigned b0 = bits[tm][y][0], b1 = bits[tm][y][1], b2 = bits[tm][y][2];
        unsigned w3[3] = { b0, b1, b2 };
        unsigned nib = (w3[x0 >> 5] >> (x0 & 31)) & 0xFFu;

        int dl = x0 - nearest_left(b0, b1, b2, x0);
        int dr = nearest_right(b0, b1, b2, x0 + 7) - (x0 + 7);

        int dlv[8], drv[8];
        dlv[0] = dl;
#pragma unroll
        for (int i = 1; i < 8; i++) dlv[i] = ((nib >> i) & 1u) ? 0 : dlv[i - 1] + 1;
        drv[7] = dr;
#pragma unroll
        for (int i = 6; i >= 0; i--) drv[i] = ((nib >> i) & 1u) ? 0 : drv[i + 1] + 1;

        unsigned v[8];
#pragma unroll
        for (int i = 0; i < 8; i++) {
            int d = min(dlv[i], drv[i]);
            v[i] = (d > 95) ? (unsigned)SENT : (unsigned)(d * d);
        }
        uint4 pk;
        pk.x = v[0] | (v[1] << 16);
        pk.y = v[2] | (v[3] << 16);
        pk.z = v[4] | (v[5] << 16);
        pk.w = v[6] | (v[7] << 16);
        ((uint4*)rowd)[idx] = pk;
    }
    __syncthreads();

    // EDT queries for this slice's 3072 px (3 iters) -> smem hist
    {
        int base = slice * (HW_ / 3), end = base + HW_ / 3;
        for (int pix = base + t; pix < end; pix += NT) {
            int y = pix / WW, x = pix - y * WW;
            if ((bits[qm][y][x >> 5] >> (x & 31)) & 1u) {
                int e = edt2q(rowd + x, y);
                atomicAdd(&hist[min(e, CAP - 1)], 1u);
            }
        }
    }
    __syncthreads();

    // flush nonzero bins to this hid's global hist (1 iter, sparse)
    {
        unsigned int v = hist[t];
        if (v) atomicAdd(&g_hist[hid][t], v);
    }

    grid_barrier(t);

    // ================= PHASE C: percentile (48 blocks) + finalize =================
    if (bx < NBLK2) {
        const unsigned int* h = g_hist[bx];
        int pc_pair = bx >> 1, pc_dir = bx & 1;
        int pc_pl = pc_pair % NC, pc_b = pc_pair / NC;

        unsigned int own = h[t];                       // 1 bin / thread

        unsigned int inc = own;
#pragma unroll
        for (int o = 1; o < 32; o <<= 1) {
            unsigned int v = __shfl_up_sync(0xffffffffu, inc, o);
            if (lane >= o) inc += v;
        }
        if (lane == 31) warp_scan[wid] = inc;
        __syncthreads();
        if (wid == 0) {
            unsigned int wv = warp_scan[lane];
            unsigned int wi = wv;
#pragma unroll
            for (int o = 1; o < 32; o <<= 1) {
                unsigned int v = __shfl_up_sync(0xffffffffu, wi, o);
                if (lane >= o) wi += v;
            }
            warp_scan[lane] = wi - wv;
            if (lane == 31) s_total = wi;
        }
        __syncthreads();
        unsigned int base = warp_scan[wid] + (inc - own);
        unsigned int mend = base + own;
        unsigned int n = s_total;

        int nm1 = (int)n - 1; if (nm1 < 0) nm1 = 0;
        float pos = 0.95f * (float)nm1;                // fp32, matches jnp
        int lo = (int)floorf(pos), hi = (int)ceilf(pos);
        float frac = pos - (float)lo;

        if (n > 0) {
            if ((unsigned int)lo >= base && (unsigned int)lo < mend) s_bin[0] = t;
            if ((unsigned int)hi >= base && (unsigned int)hi < mend) s_bin[1] = t;
        }
        __syncthreads();

        if (t == 0) {
            float val;
            if (n == 0) {
                val = __int_as_float(0x7f800000);      // +inf
            } else {
                val = sqrtf((float)s_bin[0]) * (1.0f - frac) + sqrtf((float)s_bin[1]) * frac;
            }
            g_fr[pc_b][pc_pl][pc_dir] = val;

            // ---- last-finisher writes the 18 outputs ----
            __threadfence();
            unsigned int old = atomicInc(&g_ticket, NBLK2 - 1);   // wraps -> replay-safe
            if (old == NBLK2 - 1) {
                __threadfence();
                volatile float* fr = (volatile float*)&g_fr[0][0][0];
                float F[CC], R[CC], M[CC];
                F[0] = R[0] = M[0] = 0.0f;                        // ignored class
                for (int cc = 1; cc < CC; cc++) {
                    float sf = 0.f, sr = 0.f, sm = 0.f;
                    for (int bb = 0; bb < BB; bb++) {
                        float f = fr[(bb * NC + (cc - 1)) * 2 + 0];
                        float r = fr[(bb * NC + (cc - 1)) * 2 + 1];
                        sf += f; sr += r; sm += fmaxf(f, r);
                    }
                    F[cc] = sf / (float)BB; R[cc] = sr / (float)BB; M[cc] = sm / (float)BB;
                }
                const float* vs[3] = { M, F, R };                 // MHD, FHD, RHD
                for (int k = 0; k < 3; k++) {
                    const float* v = vs[k];
                    float s = 0.f, s1v = 0.f;
                    for (int cc = 0; cc < CC; cc++) {
                        out[k * 6 + cc] = v[cc];
                        s += v[cc];
                        if (cc >= 1) s1v += v[cc];
                    }
                    out[k * 6 + 4] = s / (float)CC;
                    out[k * 6 + 5] = s1v / (float)(CC - 1);
                }
            }
        }
    }
}

extern "C" void kernel_launch(void* const* d_in, const int* in_sizes, int n_in,
                              void* d_out, int out_size) {
    const float* pred   = (const float*)d_in[0];
    const int*   labels = (const int*)d_in[1];
    float*       out    = (float*)d_out;

    (void)cudaFuncSetAttribute(k_all, cudaFuncAttributeMaxDynamicSharedMemorySize, SMEM_BYTES);
    k_all<<<NBLK, NT, SMEM_BYTES>>>(pred, labels, out);
}